// round 13
// baseline (speedup 1.0000x reference)
#include <cuda_runtime.h>
#include <cuda_bf16.h>
#include <cuda_fp16.h>
#include <stdint.h>

// LinBnA_int on GB300 via compute_103 (legacy HMMA only). Warp-specialized hybrid v3:
//   warps 8..15: HMMA m16n8k16 over K [0, 2880)   (fp16, f32 accum, exact)
//   warps 0..7 : dp4a        over K [2880, 4096)  (int8, int accum)
// Fix vs v2: merge-buffer reads use the warp-LOCAL column (was CTA-local -> OOB SMEM read).

static constexpr int B_DIM   = 8192;
static constexpr int IN_DIM  = 4096;
static constexpr int OUT_DIM = 4096;

static constexpr int BM = 128;
static constexpr int BN = 128;
static constexpr int RS = 80;                    // fp16 smem row stride

static constexpr int H_STAGES = 90;              // 90*32 = 2880 K via HMMA
static constexpr int KD_BASE  = H_STAGES * 32;   // 2880
static constexpr int KD_LEN   = IN_DIM - KD_BASE;          // 1216
static constexpr int D_STAGES = KD_LEN / 32;                // 38

// SMEM layout
static constexpr int OFF_HA  = 0;                // 2 x 10240
static constexpr int OFF_HB  = 20480;            // 2 x 10240
static constexpr int OFF_DA  = 40960;            // 2 x 4096
static constexpr int OFF_DB  = 49152;            // 2 x 4096
static constexpr int OFF_PAR = 57344;            // 2048
static constexpr int OFF_MRG = 59392;            // 8 x 8192 = 65536
static constexpr int SMEM_TOTAL = 124928;

// mode: 0 = raw int8, 1 = int32, 2 = float32, 3 = bfloat16
__device__ int g_mode;
__device__ __align__(128) __half  g_xh[(size_t)B_DIM * IN_DIM];
__device__ __align__(128) __half  g_wh[(size_t)OUT_DIM * IN_DIM];
__device__ __align__(128) int8_t  g_xi[(size_t)B_DIM * KD_LEN];
__device__ __align__(128) int8_t  g_wi[(size_t)OUT_DIM * KD_LEN];

__global__ void probe_kernel(const void* x)
{
    if (threadIdx.x != 0) return;
    const uint32_t* w32 = (const uint32_t*)x;
    bool is_i32 = true, is_f32 = true;
    for (int i = 0; i < 32; i++) {
        uint32_t u = w32[i];
        int32_t v = (int32_t)u;
        if (!(v >= -128 && v < 128)) is_i32 = false;
        float f = __uint_as_float(u);
        if (!(isfinite(f) && f == truncf(f) && fabsf(f) <= 128.0f)) is_f32 = false;
    }
    bool is_b16 = true;
    const __nv_bfloat16* h = (const __nv_bfloat16*)x;
    for (int i = 0; i < 64; i++) {
        float f = __bfloat162float(h[i]);
        if (!(isfinite(f) && f == truncf(f) && fabsf(f) <= 128.0f)) is_b16 = false;
    }
    int m = 0;
    if (is_f32)      m = 2;
    else if (is_i32) m = 1;
    else if (is_b16) m = 3;
    g_mode = m;
}

__global__ void repack_kernel(const void* xsrc, const void* wsrc)
{
    const int m = g_mode;
    const size_t NX = (size_t)B_DIM * IN_DIM;
    const size_t NW = (size_t)OUT_DIM * IN_DIM;
    const size_t total = NX + NW;
    const size_t stride = (size_t)gridDim.x * blockDim.x;
    for (size_t i = (size_t)blockIdx.x * blockDim.x + threadIdx.x; i < total; i += stride) {
        size_t xi; const void* src; __half* dh; int8_t* di;
        if (i < NX) { xi = i;      src = xsrc; dh = g_xh; di = g_xi; }
        else        { xi = i - NX; src = wsrc; dh = g_wh; di = g_wi; }
        int v;
        if (m == 0)      v = (int)((const int8_t*)src)[xi];
        else if (m == 1) v = ((const int*)src)[xi];
        else if (m == 2) v = (int)((const float*)src)[xi];
        else             v = (int)__bfloat162float(((const __nv_bfloat16*)src)[xi]);
        dh[xi] = __int2half_rn(v);
        const int k = (int)(xi & (IN_DIM - 1));
        if (k >= KD_BASE)
            di[(xi >> 12) * KD_LEN + (k - KD_BASE)] = (int8_t)v;
    }
}

// ---- helpers --------------------------------------------------------------

__device__ __forceinline__ uint32_t smem_u32(const void* p) {
    uint32_t a;
    asm("{ .reg .u64 t; cvta.to.shared.u64 t, %1; cvt.u32.u64 %0, t; }" : "=r"(a) : "l"(p));
    return a;
}
__device__ __forceinline__ void cp16(uint32_t dst, const void* src) {
    asm volatile("cp.async.cg.shared.global [%0], [%1], 16;" :: "r"(dst), "l"(src) : "memory");
}
__device__ __forceinline__ void cp_commit() { asm volatile("cp.async.commit_group;" ::: "memory"); }
template <int N> __device__ __forceinline__ void cp_wait() {
    asm volatile("cp.async.wait_group %0;" :: "n"(N) : "memory");
}
__device__ __forceinline__ void ldm_x4(uint32_t* r, uint32_t addr) {
    asm volatile("ldmatrix.sync.aligned.m8n8.x4.shared.b16 {%0,%1,%2,%3}, [%4];"
                 : "=r"(r[0]), "=r"(r[1]), "=r"(r[2]), "=r"(r[3]) : "r"(addr));
}
__device__ __forceinline__ void mma_f16(float* d, const uint32_t* a, uint32_t b0, uint32_t b1) {
    asm volatile(
        "mma.sync.aligned.m16n8k16.row.col.f32.f16.f16.f32 "
        "{%0,%1,%2,%3}, {%4,%5,%6,%7}, {%8,%9}, {%0,%1,%2,%3};"
        : "+f"(d[0]), "+f"(d[1]), "+f"(d[2]), "+f"(d[3])
        : "r"(a[0]), "r"(a[1]), "r"(a[2]), "r"(a[3]), "r"(b0), "r"(b1));
}

// ---- main kernel: 512 threads; warps 0-7 dp4a, warps 8-15 tensor ----------

__global__ __launch_bounds__(512, 1)
void linbna_ws3_kernel(const int* __restrict__ tvec,
                       const int* __restrict__ nvec,
                       const int* __restrict__ amin,
                       const int* __restrict__ amax,
                       float*     __restrict__ out)
{
    extern __shared__ char smem[];
    const uint32_t sb = smem_u32(smem);
    const int tid = threadIdx.x;
    const int wid = tid >> 5;
    const int lid = tid & 31;
    const bool is_tensor = (wid >= 8);

    const int brow = blockIdx.y * BM;
    const int bcol = blockIdx.x * BN;

    if (tid < 128) {
        *(int*)(smem + OFF_PAR + 0    + tid * 4) = tvec[bcol + tid];
        *(int*)(smem + OFF_PAR + 512  + tid * 4) = nvec[bcol + tid];
        *(int*)(smem + OFF_PAR + 1024 + tid * 4) = amin[bcol + tid];
        *(int*)(smem + OFF_PAR + 1536 + tid * 4) = amax[bcol + tid];
    }

    auto loader = [&](int w) {
        const int hb = w & 1;
        const int row = tid >> 2, ch = tid & 3;
        cp16(sb + OFF_HA + hb * 10240 + row * RS + ch * 16,
             g_xh + (size_t)(brow + row) * IN_DIM + w * 32 + ch * 8);
        cp16(sb + OFF_HB + hb * 10240 + row * RS + ch * 16,
             g_wh + (size_t)(bcol + row) * IN_DIM + w * 32 + ch * 8);
        if ((w & 1) == 0) {
            const int j = w >> 1;
            if (j < D_STAGES) {
                const int db = j & 1;
                if (tid < 256) {
                    const int r = tid >> 1, c2 = tid & 1;
                    cp16(sb + OFF_DA + db * 4096 + r * 32 + c2 * 16,
                         g_xi + (size_t)(brow + r) * KD_LEN + j * 32 + c2 * 16);
                } else {
                    const int q = tid - 256, r = q >> 1, c2 = q & 1;
                    cp16(sb + OFF_DB + db * 4096 + r * 32 + c2 * 16,
                         g_wi + (size_t)(bcol + r) * KD_LEN + j * 32 + c2 * 16);
                }
            }
        }
        cp_commit();
    };

    const int wg = is_tensor ? (wid - 8) : wid;  // 0..7 within group
    const int wm = wg & 3;                       // rows wm*32..+31
    const int wn = wg >> 2;                      // cols wn*64..+63
    const int sub = lid >> 3;
    const int srow = lid & 7;
    const int tr = lid >> 3, tc = lid & 7;

    float accF[2][8][4];
    int   accI[8][8];
    if (is_tensor) {
#pragma unroll
        for (int mt = 0; mt < 2; mt++)
#pragma unroll
            for (int nt = 0; nt < 8; nt++)
#pragma unroll
                for (int k = 0; k < 4; k++) accF[mt][nt][k] = 0.0f;
    } else {
#pragma unroll
        for (int r = 0; r < 8; r++)
#pragma unroll
            for (int c = 0; c < 8; c++) accI[r][c] = 0;
    }

    loader(0);

    for (int i = 0; i < H_STAGES; i++) {
        const int bb = i & 1;
        if (i + 1 < H_STAGES) { loader(i + 1); cp_wait<1>(); }
        else                  { cp_wait<0>(); }
        __syncthreads();

        if (is_tensor) {
            const uint32_t fA = sb + OFF_HA + bb * 10240;
            const uint32_t fB = sb + OFF_HB + bb * 10240;
#pragma unroll
            for (int s = 0; s < 2; s++) {
                uint32_t afr[2][4];
#pragma unroll
                for (int mt = 0; mt < 2; mt++) {
                    const int row = wm * 32 + mt * 16 + (sub & 1) * 8 + srow;
                    const int ch  = 2 * s + (sub >> 1);
                    ldm_x4(afr[mt], fA + row * RS + ch * 16);
                }
                uint32_t bfr[4][4];
#pragma unroll
                for (int bq = 0; bq < 4; bq++) {
                    const int nrow = wn * 64 + bq * 16 + (sub >> 1) * 8 + srow;
                    const int ch   = 2 * s + (sub & 1);
                    ldm_x4(bfr[bq], fB + nrow * RS + ch * 16);
                }
#pragma unroll
                for (int mt = 0; mt < 2; mt++)
#pragma unroll
                    for (int nt = 0; nt < 8; nt++)
                        mma_f16(accF[mt][nt], afr[mt],
                                bfr[nt >> 1][(nt & 1) * 2], bfr[nt >> 1][(nt & 1) * 2 + 1]);
            }
        } else if (i < 2 * D_STAGES) {
            const int j = i >> 1, h = i & 1;
            const char* dA = smem + OFF_DA + (j & 1) * 4096;
            const char* dB = smem + OFF_DB + (j & 1) * 4096;

            uint4 a8[8];
#pragma unroll
            for (int rr = 0; rr < 8; rr++) {
                const int row = wm * 32 + tr * 8 + rr;
                a8[rr] = *(const uint4*)(dA + row * 32 + h * 16);
            }
#pragma unroll
            for (int cc = 0; cc < 8; cc++) {
                const int col = wn * 64 + cc * 8 + tc;
                const uint4 b4 = *(const uint4*)(dB + col * 32 + h * 16);
#pragma unroll
                for (int rr = 0; rr < 8; rr++) {
                    int s = accI[rr][cc];
                    s = __dp4a((int)a8[rr].x, (int)b4.x, s);
                    s = __dp4a((int)a8[rr].y, (int)b4.y, s);
                    s = __dp4a((int)a8[rr].z, (int)b4.z, s);
                    s = __dp4a((int)a8[rr].w, (int)b4.w, s);
                    accI[rr][cc] = s;
                }
            }
        }

        __syncthreads();
    }

    // ---- merge: dp4a warps publish warp-local 32x64 int tiles ----
    if (!is_tensor) {
        char* mrg = smem + OFF_MRG + wg * 8192;
#pragma unroll
        for (int rr = 0; rr < 8; rr++)
#pragma unroll
            for (int cc = 0; cc < 8; cc++)
                *(int*)(mrg + ((tr * 8 + rr) * 64 + cc * 8 + tc) * 4) = accI[rr][cc];
    }
    __syncthreads();

    if (is_tensor) {
        const char* mrg = smem + OFF_MRG + wg * 8192;
        const int* sT  = (const int*)(smem + OFF_PAR);
        const int* sN  = (const int*)(smem + OFF_PAR + 512);
        const int* sLo = (const int*)(smem + OFF_PAR + 1024);
        const int* sHi = (const int*)(smem + OFF_PAR + 1536);

        const int r0 = brow + wm * 32 + (lid >> 2);
        const int cb = wn * 64 + 2 * (lid & 3);

#pragma unroll
        for (int mt = 0; mt < 2; mt++) {
#pragma unroll
            for (int nt = 0; nt < 8; nt++) {
                const int c  = cb + nt * 8;                  // CTA-local col (params/output)
                const int cl = 2 * (lid & 3) + nt * 8;       // warp-LOCAL col (merge buffer)
                const int gc = bcol + c;
                const int rl = mt * 16 + (lid >> 2);
                const int i00 = *(const int*)(mrg + ((rl)     * 64 + cl)     * 4);
                const int i01 = *(const int*)(mrg + ((rl)     * 64 + cl + 1) * 4);
                const int i10 = *(const int*)(mrg + ((rl + 8) * 64 + cl)     * 4);
                const int i11 = *(const int*)(mrg + ((rl + 8) * 64 + cl + 1) * 4);

                const int t0 = sT[c],  t1 = sT[c + 1];
                const int s0 = -sN[c], s1 = -sN[c + 1];
                const int l0 = sLo[c], l1 = sLo[c + 1];
                const int h0 = sHi[c], h1 = sHi[c + 1];

                int v00 = (__float2int_rn(accF[mt][nt][0]) + i00 + t0) >> s0;
                int v01 = (__float2int_rn(accF[mt][nt][1]) + i01 + t1) >> s1;
                int v10 = (__float2int_rn(accF[mt][nt][2]) + i10 + t0) >> s0;
                int v11 = (__float2int_rn(accF[mt][nt][3]) + i11 + t1) >> s1;
                v00 = min(max(v00, l0), h0);  v01 = min(max(v01, l1), h1);
                v10 = min(max(v10, l0), h0);  v11 = min(max(v11, l1), h1);

                const int ra = r0 + mt * 16;
                float2 qa = { (float)v00, (float)v01 };
                float2 qb = { (float)v10, (float)v11 };
                *(float2*)(out + (size_t)ra * OUT_DIM + gc)       = qa;
                *(float2*)(out + (size_t)(ra + 8) * OUT_DIM + gc) = qb;
            }
        }
    }
}

extern "C" void kernel_launch(void* const* d_in, const int* in_sizes, int n_in,
                              void* d_out, int out_size)
{
    const void* x   = d_in[0];
    const void* w   = d_in[1];
    const int* t    = (const int*)d_in[2];
    const int* n    = (const int*)d_in[3];
    const int* lo   = (const int*)d_in[4];
    const int* hi   = (const int*)d_in[5];

    static bool attr_set = false;
    if (!attr_set) {
        cudaFuncSetAttribute(linbna_ws3_kernel,
                             cudaFuncAttributeMaxDynamicSharedMemorySize, SMEM_TOTAL);
        attr_set = true;
    }

    probe_kernel<<<1, 32>>>(x);
    repack_kernel<<<1184, 256>>>(x, w);
    dim3 grid(OUT_DIM / BN, B_DIM / BM);   // (32, 64)
    linbna_ws3_kernel<<<grid, 512, SMEM_TOTAL>>>(t, n, lo, hi, (float*)d_out);
}

// round 14
// speedup vs baseline: 2.3273x; 2.3273x over previous
#include <cuda_runtime.h>
#include <cuda_bf16.h>
#include <cuda_fp16.h>
#include <stdint.h>

// LinBnA_int on GB300 via compute_103 (legacy HMMA only; tcgen05 unreachable, s8-IMMA emulated).
// Pure HMMA GEMM, 64x64 warp tiles (8 warps / 256 thr per 128x256 CTA tile) to cut ldmatrix
// SMEM traffic ~33% vs the 1075us 32x64 version — discriminates smem-BW-bound vs tensor-bound.
// Probe is merged into repack (2 launches/call) so ncu capture lands on the GEMM.

static constexpr int B_DIM   = 8192;
static constexpr int IN_DIM  = 4096;
static constexpr int OUT_DIM = 4096;

static constexpr int BM = 128;             // M rows per CTA
static constexpr int BN = 256;             // N cols per CTA
static constexpr int KT = IN_DIM / 32;     // 128 k16x2 stages
static constexpr int RS = 80;              // fp16 smem row stride (64B data + 16 pad)

// SMEM layout (bytes)
static constexpr int OFF_HA  = 0;          // 2 x (128*80)  = 20480
static constexpr int OFF_HB  = 20480;      // 2 x (256*80)  = 40960
static constexpr int OFF_PAR = 61440;      // 4 x 256 x 4   = 4096
static constexpr int SMEM_TOTAL = 65536;

// mode: 0 = raw int8, 1 = int32, 2 = float32, 3 = bfloat16
__device__ __align__(128) __half g_xh[(size_t)B_DIM * IN_DIM];     // 64 MB
__device__ __align__(128) __half g_wh[(size_t)OUT_DIM * IN_DIM];   // 32 MB

// repack with built-in per-block probe (deterministic: every block classifies identically)
__global__ void repack_kernel(const void* xsrc, const void* wsrc)
{
    __shared__ int s_mode;
    if (threadIdx.x == 0) {
        const uint32_t* w32 = (const uint32_t*)xsrc;
        bool is_i32 = true, is_f32 = true;
        for (int i = 0; i < 32; i++) {
            uint32_t u = w32[i];
            int32_t v = (int32_t)u;
            if (!(v >= -128 && v < 128)) is_i32 = false;
            float f = __uint_as_float(u);
            if (!(isfinite(f) && f == truncf(f) && fabsf(f) <= 128.0f)) is_f32 = false;
        }
        bool is_b16 = true;
        const __nv_bfloat16* h = (const __nv_bfloat16*)xsrc;
        for (int i = 0; i < 64; i++) {
            float f = __bfloat162float(h[i]);
            if (!(isfinite(f) && f == truncf(f) && fabsf(f) <= 128.0f)) is_b16 = false;
        }
        int m = 0;
        if (is_f32)      m = 2;
        else if (is_i32) m = 1;
        else if (is_b16) m = 3;
        s_mode = m;
    }
    __syncthreads();
    const int m = s_mode;

    const size_t NX = (size_t)B_DIM * IN_DIM;
    const size_t NW = (size_t)OUT_DIM * IN_DIM;
    const size_t total = NX + NW;
    const size_t stride = (size_t)gridDim.x * blockDim.x;
    for (size_t i = (size_t)blockIdx.x * blockDim.x + threadIdx.x; i < total; i += stride) {
        size_t xi; const void* src; __half* dh;
        if (i < NX) { xi = i;      src = xsrc; dh = g_xh; }
        else        { xi = i - NX; src = wsrc; dh = g_wh; }
        int v;
        if (m == 0)      v = (int)((const int8_t*)src)[xi];
        else if (m == 1) v = ((const int*)src)[xi];
        else if (m == 2) v = (int)((const float*)src)[xi];
        else             v = (int)__bfloat162float(((const __nv_bfloat16*)src)[xi]);
        dh[xi] = __int2half_rn(v);
    }
}

// ---- helpers --------------------------------------------------------------

__device__ __forceinline__ uint32_t smem_u32(const void* p) {
    uint32_t a;
    asm("{ .reg .u64 t; cvta.to.shared.u64 t, %1; cvt.u32.u64 %0, t; }" : "=r"(a) : "l"(p));
    return a;
}
__device__ __forceinline__ void cp16(uint32_t dst, const void* src) {
    asm volatile("cp.async.cg.shared.global [%0], [%1], 16;" :: "r"(dst), "l"(src) : "memory");
}
__device__ __forceinline__ void cp_commit() { asm volatile("cp.async.commit_group;" ::: "memory"); }
template <int N> __device__ __forceinline__ void cp_wait() {
    asm volatile("cp.async.wait_group %0;" :: "n"(N) : "memory");
}
__device__ __forceinline__ void ldm_x4(uint32_t* r, uint32_t addr) {
    asm volatile("ldmatrix.sync.aligned.m8n8.x4.shared.b16 {%0,%1,%2,%3}, [%4];"
                 : "=r"(r[0]), "=r"(r[1]), "=r"(r[2]), "=r"(r[3]) : "r"(addr));
}
__device__ __forceinline__ void mma_f16(float* d, const uint32_t* a, uint32_t b0, uint32_t b1) {
    asm volatile(
        "mma.sync.aligned.m16n8k16.row.col.f32.f16.f16.f32 "
        "{%0,%1,%2,%3}, {%4,%5,%6,%7}, {%8,%9}, {%0,%1,%2,%3};"
        : "+f"(d[0]), "+f"(d[1]), "+f"(d[2]), "+f"(d[3])
        : "r"(a[0]), "r"(a[1]), "r"(a[2]), "r"(a[3]), "r"(b0), "r"(b1));
}

// ---- main GEMM: 256 threads, 8 warps as 2(M) x 4(N), warp tile 64x64 ------

__global__ __launch_bounds__(256, 1)
void linbna_hmma64_kernel(const int* __restrict__ tvec,
                          const int* __restrict__ nvec,
                          const int* __restrict__ amin,
                          const int* __restrict__ amax,
                          float*     __restrict__ out)
{
    extern __shared__ char smem[];
    const uint32_t sb = smem_u32(smem);
    const int tid = threadIdx.x;
    const int wid = tid >> 5;
    const int lid = tid & 31;

    const int brow = blockIdx.y * BM;
    const int bcol = blockIdx.x * BN;

    // stage epilogue params (256 cols, 1 per thread)
    {
        *(int*)(smem + OFF_PAR + 0    + tid * 4) = tvec[bcol + tid];
        *(int*)(smem + OFF_PAR + 1024 + tid * 4) = nvec[bcol + tid];
        *(int*)(smem + OFF_PAR + 2048 + tid * 4) = amin[bcol + tid];
        *(int*)(smem + OFF_PAR + 3072 + tid * 4) = amax[bcol + tid];
    }

    // loader: A 512 cp16 (2/thread), B 1024 cp16 (4/thread)
    auto loader = [&](int w) {
        const int hb = w & 1;
#pragma unroll
        for (int it = 0; it < 2; it++) {
            const int c = tid + 256 * it;
            const int row = c >> 2, ch = c & 3;
            cp16(sb + OFF_HA + hb * 10240 + row * RS + ch * 16,
                 g_xh + (size_t)(brow + row) * IN_DIM + w * 32 + ch * 8);
        }
#pragma unroll
        for (int it = 0; it < 4; it++) {
            const int c = tid + 256 * it;
            const int row = c >> 2, ch = c & 3;
            cp16(sb + OFF_HB + hb * 20480 + row * RS + ch * 16,
                 g_wh + (size_t)(bcol + row) * IN_DIM + w * 32 + ch * 8);
        }
        cp_commit();
    };

    const int wm = wid & 1;       // M group: rows wm*64..+63
    const int wn = wid >> 1;      // N group: cols wn*64..+63
    const int sub = lid >> 3;
    const int srow = lid & 7;

    float acc[4][8][4];
#pragma unroll
    for (int mt = 0; mt < 4; mt++)
#pragma unroll
        for (int nt = 0; nt < 8; nt++)
#pragma unroll
            for (int k = 0; k < 4; k++) acc[mt][nt][k] = 0.0f;

    loader(0);

    for (int i = 0; i < KT; i++) {
        const int bb = i & 1;
        if (i + 1 < KT) { loader(i + 1); cp_wait<1>(); }
        else            { cp_wait<0>(); }
        __syncthreads();

        const uint32_t fA = sb + OFF_HA + bb * 10240;
        const uint32_t fB = sb + OFF_HB + bb * 20480;
#pragma unroll
        for (int s = 0; s < 2; s++) {
            uint32_t afr[4][4];
#pragma unroll
            for (int mt = 0; mt < 4; mt++) {
                const int row = wm * 64 + mt * 16 + (sub & 1) * 8 + srow;
                const int ch  = 2 * s + (sub >> 1);
                ldm_x4(afr[mt], fA + row * RS + ch * 16);
            }
            uint32_t bfr[4][4];
#pragma unroll
            for (int bq = 0; bq < 4; bq++) {
                const int nrow = wn * 64 + bq * 16 + (sub >> 1) * 8 + srow;
                const int ch   = 2 * s + (sub & 1);
                ldm_x4(bfr[bq], fB + nrow * RS + ch * 16);
            }
#pragma unroll
            for (int mt = 0; mt < 4; mt++)
#pragma unroll
                for (int nt = 0; nt < 8; nt++)
                    mma_f16(acc[mt][nt], afr[mt],
                            bfr[nt >> 1][(nt & 1) * 2], bfr[nt >> 1][(nt & 1) * 2 + 1]);
        }
        __syncthreads();
    }

    // ---- epilogue: rows wm*64+mt*16+(lid>>2)+{0,8}, cols wn*64+nt*8+2*(lid&3)+{0,1}
    const int* sT  = (const int*)(smem + OFF_PAR);
    const int* sN  = (const int*)(smem + OFF_PAR + 1024);
    const int* sLo = (const int*)(smem + OFF_PAR + 2048);
    const int* sHi = (const int*)(smem + OFF_PAR + 3072);

    const int r0 = brow + wm * 64 + (lid >> 2);
    const int cb = wn * 64 + 2 * (lid & 3);

#pragma unroll
    for (int mt = 0; mt < 4; mt++) {
#pragma unroll
        for (int nt = 0; nt < 8; nt++) {
            const int c  = cb + nt * 8;
            const int gc = bcol + c;
            const int t0 = sT[c],  t1 = sT[c + 1];
            const int s0 = -sN[c], s1 = -sN[c + 1];
            const int l0 = sLo[c], l1 = sLo[c + 1];
            const int h0 = sHi[c], h1 = sHi[c + 1];

            int v00 = (__float2int_rn(acc[mt][nt][0]) + t0) >> s0;  v00 = min(max(v00, l0), h0);
            int v01 = (__float2int_rn(acc[mt][nt][1]) + t1) >> s1;  v01 = min(max(v01, l1), h1);
            int v10 = (__float2int_rn(acc[mt][nt][2]) + t0) >> s0;  v10 = min(max(v10, l0), h0);
            int v11 = (__float2int_rn(acc[mt][nt][3]) + t1) >> s1;  v11 = min(max(v11, l1), h1);

            const int ra = r0 + mt * 16;
            float2 qa = { (float)v00, (float)v01 };
            float2 qb = { (float)v10, (float)v11 };
            *(float2*)(out + (size_t)ra * OUT_DIM + gc)       = qa;
            *(float2*)(out + (size_t)(ra + 8) * OUT_DIM + gc) = qb;
        }
    }
}

extern "C" void kernel_launch(void* const* d_in, const int* in_sizes, int n_in,
                              void* d_out, int out_size)
{
    const void* x   = d_in[0];
    const void* w   = d_in[1];
    const int* t    = (const int*)d_in[2];
    const int* n    = (const int*)d_in[3];
    const int* lo   = (const int*)d_in[4];
    const int* hi   = (const int*)d_in[5];

    static bool attr_set = false;
    if (!attr_set) {
        cudaFuncSetAttribute(linbna_hmma64_kernel,
                             cudaFuncAttributeMaxDynamicSharedMemorySize, SMEM_TOTAL);
        attr_set = true;
    }

    repack_kernel<<<1184, 256>>>(x, w);
    dim3 grid(OUT_DIM / BN, B_DIM / BM);   // (16, 64)
    linbna_hmma64_kernel<<<grid, 256, SMEM_TOTAL>>>(t, n, lo, hi, (float*)d_out);
}

// round 16
// speedup vs baseline: 2.5309x; 1.0875x over previous
#include <cuda_runtime.h>
#include <cuda_bf16.h>
#include <cuda_fp16.h>
#include <stdint.h>

// LinBnA_int on GB300 via compute_103 (legacy HMMA only). Round-14 ncu: tensor=47.6%,
// occ=12.5% (1 CTA/SM, regs=212) -> latency-bound, tensor pipe half idle. This round:
// 128x128 CTA, 8 warps of 64x32, launch_bounds(256,2) => 2 CTAs/SM (16 warps/SM) to
// keep the tensor pipe fed. Same proven fragment maps / loader / epilogue.

static constexpr int B_DIM   = 8192;
static constexpr int IN_DIM  = 4096;
static constexpr int OUT_DIM = 4096;

static constexpr int BM = 128;             // M rows per CTA
static constexpr int BN = 128;             // N cols per CTA
static constexpr int KT = IN_DIM / 32;     // 128 k16x2 stages
static constexpr int RS = 80;              // fp16 smem row stride (64B data + 16 pad)

// SMEM layout (bytes) — 43008 per CTA => 2 CTAs/SM fit
static constexpr int OFF_HA  = 0;          // 2 x (128*80) = 20480
static constexpr int OFF_HB  = 20480;      // 2 x (128*80) = 20480
static constexpr int OFF_PAR = 40960;      // 4 x 128 x 4  = 2048
static constexpr int SMEM_TOTAL = 43008;

__device__ __align__(128) __half g_xh[(size_t)B_DIM * IN_DIM];     // 64 MB
__device__ __align__(128) __half g_wh[(size_t)OUT_DIM * IN_DIM];   // 32 MB

// repack with built-in per-block probe (deterministic across blocks)
__global__ void repack_kernel(const void* xsrc, const void* wsrc)
{
    __shared__ int s_mode;
    if (threadIdx.x == 0) {
        const uint32_t* w32 = (const uint32_t*)xsrc;
        bool is_i32 = true, is_f32 = true;
        for (int i = 0; i < 32; i++) {
            uint32_t u = w32[i];
            int32_t v = (int32_t)u;
            if (!(v >= -128 && v < 128)) is_i32 = false;
            float f = __uint_as_float(u);
            if (!(isfinite(f) && f == truncf(f) && fabsf(f) <= 128.0f)) is_f32 = false;
        }
        bool is_b16 = true;
        const __nv_bfloat16* h = (const __nv_bfloat16*)xsrc;
        for (int i = 0; i < 64; i++) {
            float f = __bfloat162float(h[i]);
            if (!(isfinite(f) && f == truncf(f) && fabsf(f) <= 128.0f)) is_b16 = false;
        }
        int m = 0;
        if (is_f32)      m = 2;
        else if (is_i32) m = 1;
        else if (is_b16) m = 3;
        s_mode = m;
    }
    __syncthreads();
    const int m = s_mode;

    const size_t NX = (size_t)B_DIM * IN_DIM;
    const size_t NW = (size_t)OUT_DIM * IN_DIM;
    const size_t total = NX + NW;
    const size_t stride = (size_t)gridDim.x * blockDim.x;
    for (size_t i = (size_t)blockIdx.x * blockDim.x + threadIdx.x; i < total; i += stride) {
        size_t xi; const void* src; __half* dh;
        if (i < NX) { xi = i;      src = xsrc; dh = g_xh; }
        else        { xi = i - NX; src = wsrc; dh = g_wh; }
        int v;
        if (m == 0)      v = (int)((const int8_t*)src)[xi];
        else if (m == 1) v = ((const int*)src)[xi];
        else if (m == 2) v = (int)((const float*)src)[xi];
        else             v = (int)__bfloat162float(((const __nv_bfloat16*)src)[xi]);
        dh[xi] = __int2half_rn(v);
    }
}

// ---- helpers --------------------------------------------------------------

__device__ __forceinline__ uint32_t smem_u32(const void* p) {
    uint32_t a;
    asm("{ .reg .u64 t; cvta.to.shared.u64 t, %1; cvt.u32.u64 %0, t; }" : "=r"(a) : "l"(p));
    return a;
}
__device__ __forceinline__ void cp16(uint32_t dst, const void* src) {
    asm volatile("cp.async.cg.shared.global [%0], [%1], 16;" :: "r"(dst), "l"(src) : "memory");
}
__device__ __forceinline__ void cp_commit() { asm volatile("cp.async.commit_group;" ::: "memory"); }
template <int N> __device__ __forceinline__ void cp_wait() {
    asm volatile("cp.async.wait_group %0;" :: "n"(N) : "memory");
}
__device__ __forceinline__ void ldm_x4(uint32_t* r, uint32_t addr) {
    asm volatile("ldmatrix.sync.aligned.m8n8.x4.shared.b16 {%0,%1,%2,%3}, [%4];"
                 : "=r"(r[0]), "=r"(r[1]), "=r"(r[2]), "=r"(r[3]) : "r"(addr));
}
__device__ __forceinline__ void mma_f16(float* d, const uint32_t* a, uint32_t b0, uint32_t b1) {
    asm volatile(
        "mma.sync.aligned.m16n8k16.row.col.f32.f16.f16.f32 "
        "{%0,%1,%2,%3}, {%4,%5,%6,%7}, {%8,%9}, {%0,%1,%2,%3};"
        : "+f"(d[0]), "+f"(d[1]), "+f"(d[2]), "+f"(d[3])
        : "r"(a[0]), "r"(a[1]), "r"(a[2]), "r"(a[3]), "r"(b0), "r"(b1));
}

// ---- main GEMM: 256 threads, 8 warps as 2(M) x 4(N), warp tile 64x32, occ 2 ----

__global__ __launch_bounds__(256, 2)
void linbna_occ2_kernel(const int* __restrict__ tvec,
                        const int* __restrict__ nvec,
                        const int* __restrict__ amin,
                        const int* __restrict__ amax,
                        float*     __restrict__ out)
{
    extern __shared__ char smem[];
    const uint32_t sb = smem_u32(smem);
    const int tid = threadIdx.x;
    const int wid = tid >> 5;
    const int lid = tid & 31;

    const int brow = blockIdx.y * BM;
    const int bcol = blockIdx.x * BN;

    // stage epilogue params (128 cols)
    if (tid < 128) {
        *(int*)(smem + OFF_PAR + 0    + tid * 4) = tvec[bcol + tid];
        *(int*)(smem + OFF_PAR + 512  + tid * 4) = nvec[bcol + tid];
        *(int*)(smem + OFF_PAR + 1024 + tid * 4) = amin[bcol + tid];
        *(int*)(smem + OFF_PAR + 1536 + tid * 4) = amax[bcol + tid];
    }

    // loader: A 512 cp16 (2/thread), B 512 cp16 (2/thread)
    auto loader = [&](int w) {
        const int hb = w & 1;
#pragma unroll
        for (int it = 0; it < 2; it++) {
            const int c = tid + 256 * it;
            const int row = c >> 2, ch = c & 3;
            cp16(sb + OFF_HA + hb * 10240 + row * RS + ch * 16,
                 g_xh + (size_t)(brow + row) * IN_DIM + w * 32 + ch * 8);
            cp16(sb + OFF_HB + hb * 10240 + row * RS + ch * 16,
                 g_wh + (size_t)(bcol + row) * IN_DIM + w * 32 + ch * 8);
        }
        cp_commit();
    };

    const int wm = wid & 1;       // M group: rows wm*64..+63
    const int wn = wid >> 1;      // N group: cols wn*32..+31
    const int sub = lid >> 3;
    const int srow = lid & 7;

    float acc[4][4][4];
#pragma unroll
    for (int mt = 0; mt < 4; mt++)
#pragma unroll
        for (int nt = 0; nt < 4; nt++)
#pragma unroll
            for (int k = 0; k < 4; k++) acc[mt][nt][k] = 0.0f;

    loader(0);

    for (int i = 0; i < KT; i++) {
        const int bb = i & 1;
        if (i + 1 < KT) { loader(i + 1); cp_wait<1>(); }
        else            { cp_wait<0>(); }
        __syncthreads();

        const uint32_t fA = sb + OFF_HA + bb * 10240;
        const uint32_t fB = sb + OFF_HB + bb * 10240;
#pragma unroll
        for (int s = 0; s < 2; s++) {
            uint32_t afr[4][4];
#pragma unroll
            for (int mt = 0; mt < 4; mt++) {
                const int row = wm * 64 + mt * 16 + (sub & 1) * 8 + srow;
                const int ch  = 2 * s + (sub >> 1);
                ldm_x4(afr[mt], fA + row * RS + ch * 16);
            }
            uint32_t bfr[2][4];
#pragma unroll
            for (int bq = 0; bq < 2; bq++) {
                const int nrow = wn * 32 + bq * 16 + (sub >> 1) * 8 + srow;
                const int ch   = 2 * s + (sub & 1);
                ldm_x4(bfr[bq], fB + nrow * RS + ch * 16);
            }
#pragma unroll
            for (int mt = 0; mt < 4; mt++)
#pragma unroll
                for (int nt = 0; nt < 4; nt++)
                    mma_f16(acc[mt][nt], afr[mt],
                            bfr[nt >> 1][(nt & 1) * 2], bfr[nt >> 1][(nt & 1) * 2 + 1]);
        }
        __syncthreads();
    }

    // ---- epilogue: rows wm*64+mt*16+(lid>>2)+{0,8}, cols wn*32+nt*8+2*(lid&3)+{0,1}
    const int* sT  = (const int*)(smem + OFF_PAR);
    const int* sN  = (const int*)(smem + OFF_PAR + 512);
    const int* sLo = (const int*)(smem + OFF_PAR + 1024);
    const int* sHi = (const int*)(smem + OFF_PAR + 1536);

    const int r0 = brow + wm * 64 + (lid >> 2);
    const int cb = wn * 32 + 2 * (lid & 3);

#pragma unroll
    for (int mt = 0; mt < 4; mt++) {
#pragma unroll
        for (int nt = 0; nt < 4; nt++) {
            const int c  = cb + nt * 8;
            const int gc = bcol + c;
            const int t0 = sT[c],  t1 = sT[c + 1];
            const int s0 = -sN[c], s1 = -sN[c + 1];
            const int l0 = sLo[c], l1 = sLo[c + 1];
            const int h0 = sHi[c], h1 = sHi[c + 1];

            int v00 = (__float2int_rn(acc[mt][nt][0]) + t0) >> s0;  v00 = min(max(v00, l0), h0);
            int v01 = (__float2int_rn(acc[mt][nt][1]) + t1) >> s1;  v01 = min(max(v01, l1), h1);
            int v10 = (__float2int_rn(acc[mt][nt][2]) + t0) >> s0;  v10 = min(max(v10, l0), h0);
            int v11 = (__float2int_rn(acc[mt][nt][3]) + t1) >> s1;  v11 = min(max(v11, l1), h1);

            const int ra = r0 + mt * 16;
            float2 qa = { (float)v00, (float)v01 };
            float2 qb = { (float)v10, (float)v11 };
            *(float2*)(out + (size_t)ra * OUT_DIM + gc)       = qa;
            *(float2*)(out + (size_t)(ra + 8) * OUT_DIM + gc) = qb;
        }
    }
}

extern "C" void kernel_launch(void* const* d_in, const int* in_sizes, int n_in,
                              void* d_out, int out_size)
{
    const void* x   = d_in[0];
    const void* w   = d_in[1];
    const int* t    = (const int*)d_in[2];
    const int* n    = (const int*)d_in[3];
    const int* lo   = (const int*)d_in[4];
    const int* hi   = (const int*)d_in[5];

    static bool attr_set = false;
    if (!attr_set) {
        cudaFuncSetAttribute(linbna_occ2_kernel,
                             cudaFuncAttributeMaxDynamicSharedMemorySize, SMEM_TOTAL);
        attr_set = true;
    }

    repack_kernel<<<1184, 256>>>(x, w);
    dim3 grid(OUT_DIM / BN, B_DIM / BM);   // (32, 64)
    linbna_occ2_kernel<<<grid, 256, SMEM_TOTAL>>>(t, n, lo, hi, (float*)d_out);
}

// round 17
// speedup vs baseline: 2.7880x; 1.1016x over previous
#include <cuda_runtime.h>
#include <cuda_bf16.h>
#include <cuda_fp16.h>
#include <stdint.h>

// LinBnA_int on GB300 via compute_103 (legacy HMMA only). Round-16 ncu: tensor=52.5%,
// occ=24.2%, L1=45% — residual limiter is the 2 barriers per 32-K stage. This round:
// 3-buffer cp.async ring with prefetch depth 1 => the trailing __syncthreads is provably
// removable ((D+1) mod S != 0), halving barrier count. Otherwise identical to round 16.

static constexpr int B_DIM   = 8192;
static constexpr int IN_DIM  = 4096;
static constexpr int OUT_DIM = 4096;

static constexpr int BM = 128;             // M rows per CTA
static constexpr int BN = 128;             // N cols per CTA
static constexpr int KT = IN_DIM / 32;     // 128 stages
static constexpr int RS = 80;              // fp16 smem row stride (64B data + 16 pad)

// SMEM layout (bytes) — 63488 per CTA => 2 CTAs/SM still fit (127 KB/SM)
static constexpr int OFF_HA  = 0;          // 3 x (128*80) = 30720
static constexpr int OFF_HB  = 30720;      // 3 x (128*80) = 30720
static constexpr int OFF_PAR = 61440;      // 4 x 128 x 4  = 2048
static constexpr int SMEM_TOTAL = 63488;

__device__ __align__(128) __half g_xh[(size_t)B_DIM * IN_DIM];     // 64 MB
__device__ __align__(128) __half g_wh[(size_t)OUT_DIM * IN_DIM];   // 32 MB

// repack with built-in per-block probe (deterministic across blocks)
__global__ void repack_kernel(const void* xsrc, const void* wsrc)
{
    __shared__ int s_mode;
    if (threadIdx.x == 0) {
        const uint32_t* w32 = (const uint32_t*)xsrc;
        bool is_i32 = true, is_f32 = true;
        for (int i = 0; i < 32; i++) {
            uint32_t u = w32[i];
            int32_t v = (int32_t)u;
            if (!(v >= -128 && v < 128)) is_i32 = false;
            float f = __uint_as_float(u);
            if (!(isfinite(f) && f == truncf(f) && fabsf(f) <= 128.0f)) is_f32 = false;
        }
        bool is_b16 = true;
        const __nv_bfloat16* h = (const __nv_bfloat16*)xsrc;
        for (int i = 0; i < 64; i++) {
            float f = __bfloat162float(h[i]);
            if (!(isfinite(f) && f == truncf(f) && fabsf(f) <= 128.0f)) is_b16 = false;
        }
        int m = 0;
        if (is_f32)      m = 2;
        else if (is_i32) m = 1;
        else if (is_b16) m = 3;
        s_mode = m;
    }
    __syncthreads();
    const int m = s_mode;

    const size_t NX = (size_t)B_DIM * IN_DIM;
    const size_t NW = (size_t)OUT_DIM * IN_DIM;
    const size_t total = NX + NW;
    const size_t stride = (size_t)gridDim.x * blockDim.x;
    for (size_t i = (size_t)blockIdx.x * blockDim.x + threadIdx.x; i < total; i += stride) {
        size_t xi; const void* src; __half* dh;
        if (i < NX) { xi = i;      src = xsrc; dh = g_xh; }
        else        { xi = i - NX; src = wsrc; dh = g_wh; }
        int v;
        if (m == 0)      v = (int)((const int8_t*)src)[xi];
        else if (m == 1) v = ((const int*)src)[xi];
        else if (m == 2) v = (int)((const float*)src)[xi];
        else             v = (int)__bfloat162float(((const __nv_bfloat16*)src)[xi]);
        dh[xi] = __int2half_rn(v);
    }
}

// ---- helpers --------------------------------------------------------------

__device__ __forceinline__ uint32_t smem_u32(const void* p) {
    uint32_t a;
    asm("{ .reg .u64 t; cvta.to.shared.u64 t, %1; cvt.u32.u64 %0, t; }" : "=r"(a) : "l"(p));
    return a;
}
__device__ __forceinline__ void cp16(uint32_t dst, const void* src) {
    asm volatile("cp.async.cg.shared.global [%0], [%1], 16;" :: "r"(dst), "l"(src) : "memory");
}
__device__ __forceinline__ void cp_commit() { asm volatile("cp.async.commit_group;" ::: "memory"); }
template <int N> __device__ __forceinline__ void cp_wait() {
    asm volatile("cp.async.wait_group %0;" :: "n"(N) : "memory");
}
__device__ __forceinline__ void ldm_x4(uint32_t* r, uint32_t addr) {
    asm volatile("ldmatrix.sync.aligned.m8n8.x4.shared.b16 {%0,%1,%2,%3}, [%4];"
                 : "=r"(r[0]), "=r"(r[1]), "=r"(r[2]), "=r"(r[3]) : "r"(addr));
}
__device__ __forceinline__ void mma_f16(float* d, const uint32_t* a, uint32_t b0, uint32_t b1) {
    asm volatile(
        "mma.sync.aligned.m16n8k16.row.col.f32.f16.f16.f32 "
        "{%0,%1,%2,%3}, {%4,%5,%6,%7}, {%8,%9}, {%0,%1,%2,%3};"
        : "+f"(d[0]), "+f"(d[1]), "+f"(d[2]), "+f"(d[3])
        : "r"(a[0]), "r"(a[1]), "r"(a[2]), "r"(a[3]), "r"(b0), "r"(b1));
}

// ---- main GEMM: 256 threads, 8 warps as 2(M) x 4(N), warp tile 64x32, occ 2 ----

__global__ __launch_bounds__(256, 2)
void linbna_ring3_kernel(const int* __restrict__ tvec,
                         const int* __restrict__ nvec,
                         const int* __restrict__ amin,
                         const int* __restrict__ amax,
                         float*     __restrict__ out)
{
    extern __shared__ char smem[];
    const uint32_t sb = smem_u32(smem);
    const int tid = threadIdx.x;
    const int wid = tid >> 5;
    const int lid = tid & 31;

    const int brow = blockIdx.y * BM;
    const int bcol = blockIdx.x * BN;

    if (tid < 128) {
        *(int*)(smem + OFF_PAR + 0    + tid * 4) = tvec[bcol + tid];
        *(int*)(smem + OFF_PAR + 512  + tid * 4) = nvec[bcol + tid];
        *(int*)(smem + OFF_PAR + 1024 + tid * 4) = amin[bcol + tid];
        *(int*)(smem + OFF_PAR + 1536 + tid * 4) = amax[bcol + tid];
    }

    // loader: A 512 cp16 (2/thread), B 512 cp16 (2/thread); ring buffer w % 3
    auto loader = [&](int w) {
        const int hb = w % 3;
#pragma unroll
        for (int it = 0; it < 2; it++) {
            const int c = tid + 256 * it;
            const int row = c >> 2, ch = c & 3;
            cp16(sb + OFF_HA + hb * 10240 + row * RS + ch * 16,
                 g_xh + (size_t)(brow + row) * IN_DIM + w * 32 + ch * 8);
            cp16(sb + OFF_HB + hb * 10240 + row * RS + ch * 16,
                 g_wh + (size_t)(bcol + row) * IN_DIM + w * 32 + ch * 8);
        }
        cp_commit();
    };

    const int wm = wid & 1;       // rows wm*64..+63
    const int wn = wid >> 1;      // cols wn*32..+31
    const int sub = lid >> 3;
    const int srow = lid & 7;

    float acc[4][4][4];
#pragma unroll
    for (int mt = 0; mt < 4; mt++)
#pragma unroll
        for (int nt = 0; nt < 4; nt++)
#pragma unroll
            for (int k = 0; k < 4; k++) acc[mt][nt][k] = 0.0f;

    loader(0);

    for (int i = 0; i < KT; i++) {
        const int bb = i % 3;
        if (i + 1 < KT) { loader(i + 1); cp_wait<1>(); }
        else            { cp_wait<0>(); }
        __syncthreads();     // single barrier per stage (3-buffer ring makes WAR-safe)

        const uint32_t fA = sb + OFF_HA + bb * 10240;
        const uint32_t fB = sb + OFF_HB + bb * 10240;
#pragma unroll
        for (int s = 0; s < 2; s++) {
            uint32_t afr[4][4];
#pragma unroll
            for (int mt = 0; mt < 4; mt++) {
                const int row = wm * 64 + mt * 16 + (sub & 1) * 8 + srow;
                const int ch  = 2 * s + (sub >> 1);
                ldm_x4(afr[mt], fA + row * RS + ch * 16);
            }
            uint32_t bfr[2][4];
#pragma unroll
            for (int bq = 0; bq < 2; bq++) {
                const int nrow = wn * 32 + bq * 16 + (sub >> 1) * 8 + srow;
                const int ch   = 2 * s + (sub & 1);
                ldm_x4(bfr[bq], fB + nrow * RS + ch * 16);
            }
#pragma unroll
            for (int mt = 0; mt < 4; mt++)
#pragma unroll
                for (int nt = 0; nt < 4; nt++)
                    mma_f16(acc[mt][nt], afr[mt],
                            bfr[nt >> 1][(nt & 1) * 2], bfr[nt >> 1][(nt & 1) * 2 + 1]);
        }
        // no trailing __syncthreads: fast warps write buffer (i+2)%3, readers use i%3
    }

    // ---- epilogue
    const int* sT  = (const int*)(smem + OFF_PAR);
    const int* sN  = (const int*)(smem + OFF_PAR + 512);
    const int* sLo = (const int*)(smem + OFF_PAR + 1024);
    const int* sHi = (const int*)(smem + OFF_PAR + 1536);

    const int r0 = brow + wm * 64 + (lid >> 2);
    const int cb = wn * 32 + 2 * (lid & 3);

#pragma unroll
    for (int mt = 0; mt < 4; mt++) {
#pragma unroll
        for (int nt = 0; nt < 4; nt++) {
            const int c  = cb + nt * 8;
            const int gc = bcol + c;
            const int t0 = sT[c],  t1 = sT[c + 1];
            const int s0 = -sN[c], s1 = -sN[c + 1];
            const int l0 = sLo[c], l1 = sLo[c + 1];
            const int h0 = sHi[c], h1 = sHi[c + 1];

            int v00 = (__float2int_rn(acc[mt][nt][0]) + t0) >> s0;  v00 = min(max(v00, l0), h0);
            int v01 = (__float2int_rn(acc[mt][nt][1]) + t1) >> s1;  v01 = min(max(v01, l1), h1);
            int v10 = (__float2int_rn(acc[mt][nt][2]) + t0) >> s0;  v10 = min(max(v10, l0), h0);
            int v11 = (__float2int_rn(acc[mt][nt][3]) + t1) >> s1;  v11 = min(max(v11, l1), h1);

            const int ra = r0 + mt * 16;
            float2 qa = { (float)v00, (float)v01 };
            float2 qb = { (float)v10, (float)v11 };
            *(float2*)(out + (size_t)ra * OUT_DIM + gc)       = qa;
            *(float2*)(out + (size_t)(ra + 8) * OUT_DIM + gc) = qb;
        }
    }
}

extern "C" void kernel_launch(void* const* d_in, const int* in_sizes, int n_in,
                              void* d_out, int out_size)
{
    const void* x   = d_in[0];
    const void* w   = d_in[1];
    const int* t    = (const int*)d_in[2];
    const int* n    = (const int*)d_in[3];
    const int* lo   = (const int*)d_in[4];
    const int* hi   = (const int*)d_in[5];

    static bool attr_set = false;
    if (!attr_set) {
        cudaFuncSetAttribute(linbna_ring3_kernel,
                             cudaFuncAttributeMaxDynamicSharedMemorySize, SMEM_TOTAL);
        attr_set = true;
    }

    repack_kernel<<<1184, 256>>>(x, w);
    dim3 grid(OUT_DIM / BN, B_DIM / BM);   // (32, 64)
    linbna_ring3_kernel<<<grid, 256, SMEM_TOTAL>>>(t, n, lo, hi, (float*)d_out);
}